// round 7
// baseline (speedup 1.0000x reference)
#include <cuda_runtime.h>
#include <cstdint>

// Problem constants
constexpr int Bb = 8, Tt = 1024, Dd = 512, Hh = 8, KDk = 64;
constexpr int BT = Bb * Tt;          // 8192
constexpr int HD = Hh * KDk;         // 512
constexpr int OUT_ELEMS = Bb * Tt * Dd;  // offset of attn_weights in d_out

// Scratch (allocation-free: device globals). 16B alignment for float4 access.
__device__ __align__(16) float g_qh[BT * HD];
__device__ __align__(16) float g_kh[BT * HD];
__device__ __align__(16) float g_vh[BT * HD];
__device__ __align__(16) float g_att[BT * HD];

// ---------------------------------------------------------------------------
// tf32 split helpers (3xTF32 scheme): x ~= hi + lo, each tf32.
// ---------------------------------------------------------------------------
__device__ __forceinline__ uint32_t f2tf(float x) {
    uint32_t r; asm("cvt.rna.tf32.f32 %0, %1;" : "=r"(r) : "f"(x)); return r;
}
__device__ __forceinline__ uint2 split2(float x) {
    uint32_t hi = f2tf(x);
    float lo = x - __uint_as_float(hi);
    return make_uint2(hi, f2tf(lo));
}
__device__ __forceinline__ void mma8(float* c, uint32_t a0, uint32_t a1,
                                     uint32_t a2, uint32_t a3,
                                     uint32_t b0, uint32_t b1) {
    asm volatile(
        "mma.sync.aligned.m16n8k8.row.col.f32.tf32.tf32.f32 "
        "{%0,%1,%2,%3},{%4,%5,%6,%7},{%8,%9},{%0,%1,%2,%3};"
        : "+f"(c[0]), "+f"(c[1]), "+f"(c[2]), "+f"(c[3])
        : "r"(a0), "r"(a1), "r"(a2), "r"(a3), "r"(b0), "r"(b1));
}

// ---------------------------------------------------------------------------
// Fragment-packed smem layouts (uint2 = {hi,lo} per element).
// A-pack (m16k8 frags, row-major A): [rowblk16][kstep8][lane][slot0..3]
//   slots per lane t: s0=(t/4, t%4) s1=(t/4+8, t%4) s2=(t/4, t%4+4) s3=(t/4+8, t%4+4)
// B-pack (k8n8 frags, col-major B): [nblk8][kstep8][lane][slot0..1]
//   slots per lane t: s0=(k=t%4, n=t/4) s1=(k=t%4+4, n=t/4)
// Reads are one/two LDS.128 per fragment pair, conflict-free.
// ---------------------------------------------------------------------------
__device__ __forceinline__ int apk_idx(int r, int c) {   // uint2 index
    int rowblk = r >> 4, r16 = r & 15, ks = c >> 3, c8 = c & 7;
    int lane = ((r16 & 7) << 2) | (c8 & 3);
    int slot = ((c8 >> 2) << 1) | (r16 >> 3);
    return ((((rowblk << 2) + ks) << 5) + lane) * 4 + slot;
}
__device__ __forceinline__ int bpk_idx(int k, int n) {   // uint2 index
    int nblk = n >> 3, n8 = n & 7, ks = k >> 3, k8 = k & 7;
    int lane = (n8 << 2) | (k8 & 3);
    int slot = k8 >> 2;
    return ((((nblk << 2) + ks) << 5) + lane) * 2 + slot;
}

// Warp-level MMA over one staged 32-deep k-chunk. Warp tile = MI*16 x NJ*8.
// acc layout: m16n8 C frag: c0=(t/4, 2(t%4)) c1=+1col c2/(c3)=(row+8).
template <int MI, int NJ>
__device__ __forceinline__ void warp_chunk(const uint4* __restrict__ Apk,
                                           const uint4* __restrict__ Bpk,
                                           int wrblk, int wcblk, int lane,
                                           float acc[MI][NJ][4]) {
#pragma unroll
    for (int ks = 0; ks < 4; ks++) {
        uint4 bb[NJ];
#pragma unroll
        for (int nj = 0; nj < NJ; nj++)
            bb[nj] = Bpk[((wcblk + nj) * 4 + ks) * 32 + lane];
#pragma unroll
        for (int mi = 0; mi < MI; mi++) {
            const uint4* ap = &Apk[(((wrblk + mi) * 4 + ks) * 32 + lane) * 2];
            uint4 a0 = ap[0], a1 = ap[1];
            // a_hi = {a0.x,a0.z,a1.x,a1.z}; a_lo = {a0.y,a0.w,a1.y,a1.w}
#pragma unroll
            for (int nj = 0; nj < NJ; nj++) {
                mma8(acc[mi][nj], a0.x, a0.z, a1.x, a1.z, bb[nj].x, bb[nj].z); // hi*hi
                mma8(acc[mi][nj], a0.y, a0.w, a1.y, a1.w, bb[nj].x, bb[nj].z); // lo*hi
                mma8(acc[mi][nj], a0.x, a0.z, a1.x, a1.z, bb[nj].y, bb[nj].w); // hi*lo
            }
        }
    }
}

// ---------------------------------------------------------------------------
// 128x128-tile GEMM, K=512: C = A[8192,512] @ B[512,512]. 8 warps (2x4),
// warp tile 64x32. Staged k-chunks of 32, smem 64KB (A-pack 32K + B-pack 32K).
// ---------------------------------------------------------------------------
__device__ __forceinline__ void gemm512_core(const float* __restrict__ A,
                                             const float* __restrict__ B,
                                             float* __restrict__ C, char* sm) {
    uint2* Apk2 = (uint2*)sm;
    uint2* Bpk2 = (uint2*)(sm + 32768);
    const uint4* Apk4 = (const uint4*)Apk2;
    const uint4* Bpk4 = (const uint4*)Bpk2;

    const int tid = threadIdx.x, lane = tid & 31, warp = tid >> 5;
    const int row0 = blockIdx.y * 128, col0 = blockIdx.x * 128;
    const int wrblk = (warp >> 2) * 4;   // 16-row units
    const int wcblk = (warp & 3) * 4;    // 8-col units

    float acc[4][4][4];
#pragma unroll
    for (int i = 0; i < 4; i++)
#pragma unroll
        for (int j = 0; j < 4; j++)
#pragma unroll
            for (int q = 0; q < 4; q++) acc[i][j][q] = 0.f;

    const int ar = tid >> 1, ac = (tid & 1) * 16;       // A: row, 16 cols
    const int bk = tid >> 3, bn = (tid & 7) * 16;       // B: k-row, 16 cols

    for (int k0 = 0; k0 < 512; k0 += 32) {
        __syncthreads();
        {
            const float* ap = A + (size_t)(row0 + ar) * 512 + k0 + ac;
#pragma unroll
            for (int q = 0; q < 16; q += 4) {
                float4 v = *(const float4*)(ap + q);
                Apk2[apk_idx(ar, ac + q + 0)] = split2(v.x);
                Apk2[apk_idx(ar, ac + q + 1)] = split2(v.y);
                Apk2[apk_idx(ar, ac + q + 2)] = split2(v.z);
                Apk2[apk_idx(ar, ac + q + 3)] = split2(v.w);
            }
            const float* bp = B + (size_t)(k0 + bk) * 512 + col0 + bn;
#pragma unroll
            for (int q = 0; q < 16; q += 4) {
                float4 v = *(const float4*)(bp + q);
                Bpk2[bpk_idx(bk, bn + q + 0)] = split2(v.x);
                Bpk2[bpk_idx(bk, bn + q + 1)] = split2(v.y);
                Bpk2[bpk_idx(bk, bn + q + 2)] = split2(v.z);
                Bpk2[bpk_idx(bk, bn + q + 3)] = split2(v.w);
            }
        }
        __syncthreads();
        warp_chunk<4, 4>(Apk4, Bpk4, wrblk, wcblk, lane, acc);
    }

    const int r0 = row0 + (warp >> 2) * 64 + (lane >> 2);
    const int c0 = col0 + (warp & 3) * 32 + (lane & 3) * 2;
#pragma unroll
    for (int mi = 0; mi < 4; mi++)
#pragma unroll
        for (int nj = 0; nj < 4; nj++) {
            const int r = r0 + mi * 16, c = c0 + nj * 8;
            *(float2*)(C + (size_t)r * 512 + c)       = make_float2(acc[mi][nj][0], acc[mi][nj][1]);
            *(float2*)(C + (size_t)(r + 8) * 512 + c) = make_float2(acc[mi][nj][2], acc[mi][nj][3]);
        }
}

__global__ __launch_bounds__(256)
void proj3_tc(const float* __restrict__ q, const float* __restrict__ k,
              const float* __restrict__ v,
              const float* __restrict__ Wq, const float* __restrict__ Wk,
              const float* __restrict__ Wv,
              float* __restrict__ qh, float* __restrict__ kh,
              float* __restrict__ vh) {
    extern __shared__ char sm[];
    const float* A; const float* Bm; float* C;
    if (blockIdx.z == 0)      { A = q; Bm = Wq; C = qh; }
    else if (blockIdx.z == 1) { A = k; Bm = Wk; C = kh; }
    else                      { A = v; Bm = Wv; C = vh; }
    gemm512_core(A, Bm, C, sm);
}

__global__ __launch_bounds__(256)
void outproj_tc(const float* __restrict__ att, const float* __restrict__ Wo,
                float* __restrict__ out) {
    extern __shared__ char sm[];
    gemm512_core(att, Wo, out, sm);
}

// ---------------------------------------------------------------------------
// RBF weights, tensor-core: per block one 128(q)x128(k) tile of
// W = exp(2*QK^T - |q|^2 - |k|^2). K=64 in 2 chunks of 32. smem 66KB.
// ---------------------------------------------------------------------------
__global__ __launch_bounds__(256)
void rbf_tc(const float* __restrict__ qh, const float* __restrict__ kh,
            float* __restrict__ W) {
    extern __shared__ char sm[];
    uint2* Apk2 = (uint2*)sm;
    uint2* Bpk2 = (uint2*)(sm + 32768);
    const uint4* Apk4 = (const uint4*)Apk2;
    const uint4* Bpk4 = (const uint4*)Bpk2;
    float* q2s = (float*)(sm + 65536);
    float* k2s = q2s + 128;

    const int tid = threadIdx.x, lane = tid & 31, warp = tid >> 5;
    const int kt = blockIdx.x, qt = blockIdx.y, bh = blockIdx.z;
    const int b = bh >> 3, h = bh & 7;

    const float* qbase = qh + (size_t)(b * Tt + qt * 128) * HD + h * 64;
    const float* kbase = kh + (size_t)(b * Tt + kt * 128) * HD + h * 64;

    // Row norms from gmem (fp32)
    if (tid < 128) {
        const float* p = qbase + (size_t)tid * HD;
        float s = 0.f;
#pragma unroll
        for (int c = 0; c < 64; c += 4) {
            float4 x = *(const float4*)(p + c);
            s = fmaf(x.x, x.x, s); s = fmaf(x.y, x.y, s);
            s = fmaf(x.z, x.z, s); s = fmaf(x.w, x.w, s);
        }
        q2s[tid] = s;
    } else {
        const int r = tid - 128;
        const float* p = kbase + (size_t)r * HD;
        float s = 0.f;
#pragma unroll
        for (int c = 0; c < 64; c += 4) {
            float4 x = *(const float4*)(p + c);
            s = fmaf(x.x, x.x, s); s = fmaf(x.y, x.y, s);
            s = fmaf(x.z, x.z, s); s = fmaf(x.w, x.w, s);
        }
        k2s[r] = s;
    }

    const int wrblk = (warp >> 2) * 4;
    const int wcblk = (warp & 3) * 4;

    float acc[4][4][4];
#pragma unroll
    for (int i = 0; i < 4; i++)
#pragma unroll
        for (int j = 0; j < 4; j++)
#pragma unroll
            for (int q = 0; q < 4; q++) acc[i][j][q] = 0.f;

    const int ar = tid >> 1, ac = (tid & 1) * 16;

    for (int k0 = 0; k0 < 64; k0 += 32) {
        __syncthreads();
        {
            const float* ap = qbase + (size_t)ar * HD + k0 + ac;
#pragma unroll
            for (int q = 0; q < 16; q += 4) {
                float4 x = *(const float4*)(ap + q);
                Apk2[apk_idx(ar, ac + q + 0)] = split2(x.x);
                Apk2[apk_idx(ar, ac + q + 1)] = split2(x.y);
                Apk2[apk_idx(ar, ac + q + 2)] = split2(x.z);
                Apk2[apk_idx(ar, ac + q + 3)] = split2(x.w);
            }
            // K-tile: token row -> B-pack column (n), kd -> k
            const float* kp = kbase + (size_t)ar * HD + k0 + ac;
#pragma unroll
            for (int q = 0; q < 16; q += 4) {
                float4 x = *(const float4*)(kp + q);
                Bpk2[bpk_idx(ac + q + 0, ar)] = split2(x.x);
                Bpk2[bpk_idx(ac + q + 1, ar)] = split2(x.y);
                Bpk2[bpk_idx(ac + q + 2, ar)] = split2(x.z);
                Bpk2[bpk_idx(ac + q + 3, ar)] = split2(x.w);
            }
        }
        __syncthreads();
        warp_chunk<4, 4>(Apk4, Bpk4, wrblk, wcblk, lane, acc);
    }

    // Epilogue: exp(2S - q2 - k2) straight from C-fragments
    const int rl0 = (warp >> 2) * 64 + (lane >> 2);
    const int cl0 = (warp & 3) * 32 + (lane & 3) * 2;
    float* wb = W + ((size_t)bh * Tt + qt * 128) * Tt + kt * 128;
#pragma unroll
    for (int mi = 0; mi < 4; mi++)
#pragma unroll
        for (int nj = 0; nj < 4; nj++) {
            const int rl = rl0 + mi * 16, cl = cl0 + nj * 8;
            const float qa = q2s[rl], qb = q2s[rl + 8];
            const float ka = k2s[cl], kb = k2s[cl + 1];
            float2 v0, v1;
            v0.x = __expf(2.f * acc[mi][nj][0] - qa - ka);
            v0.y = __expf(2.f * acc[mi][nj][1] - qa - kb);
            v1.x = __expf(2.f * acc[mi][nj][2] - qb - ka);
            v1.y = __expf(2.f * acc[mi][nj][3] - qb - kb);
            *(float2*)(wb + (size_t)rl * Tt + cl)       = v0;
            *(float2*)(wb + (size_t)(rl + 8) * Tt + cl) = v1;
        }
}

// ---------------------------------------------------------------------------
// attn = W @ V per (b,h): block 128x64, K=1024 in chunks of 32. 8 warps (4x2),
// warp tile 32x32. smem 48KB (A-pack 32K + B-pack 16K).
// ---------------------------------------------------------------------------
__global__ __launch_bounds__(256)
void wv_tc(const float* __restrict__ W, const float* __restrict__ vh,
           float* __restrict__ att) {
    extern __shared__ char sm[];
    uint2* Apk2 = (uint2*)sm;
    uint2* Bpk2 = (uint2*)(sm + 32768);
    const uint4* Apk4 = (const uint4*)Apk2;
    const uint4* Bpk4 = (const uint4*)Bpk2;

    const int tid = threadIdx.x, lane = tid & 31, warp = tid >> 5;
    const int qt = blockIdx.x, bh = blockIdx.y;
    const int b = bh >> 3, h = bh & 7;

    const float* wbase = W + ((size_t)bh * Tt + qt * 128) * Tt;
    const float* vbase = vh + (size_t)(b * Tt) * HD + h * 64;

    const int wrblk = (warp >> 1) * 2;   // 16-row units (32 rows/warp)
    const int wcblk = (warp & 1) * 4;    // 8-col units (32 cols/warp)

    float acc[2][4][4];
#pragma unroll
    for (int i = 0; i < 2; i++)
#pragma unroll
        for (int j = 0; j < 4; j++)
#pragma unroll
            for (int q = 0; q < 4; q++) acc[i][j][q] = 0.f;

    const int ar = tid >> 1, ac = (tid & 1) * 16;   // W staging
    const int vk = tid >> 3, vn = (tid & 7) * 8;    // V staging

    for (int k0 = 0; k0 < Tt; k0 += 32) {
        __syncthreads();
        {
            const float* ap = wbase + (size_t)ar * Tt + k0 + ac;
#pragma unroll
            for (int q = 0; q < 16; q += 4) {
                float4 x = *(const float4*)(ap + q);
                Apk2[apk_idx(ar, ac + q + 0)] = split2(x.x);
                Apk2[apk_idx(ar, ac + q + 1)] = split2(x.y);
                Apk2[apk_idx(ar, ac + q + 2)] = split2(x.z);
                Apk2[apk_idx(ar, ac + q + 3)] = split2(x.w);
            }
            const float* vp = vbase + (size_t)(k0 + vk) * HD + vn;
#pragma unroll
            for (int q = 0; q < 8; q += 4) {
                float4 x = *(const float4*)(vp + q);
                Bpk2[bpk_idx(vk, vn + q + 0)] = split2(x.x);
                Bpk2[bpk_idx(vk, vn + q + 1)] = split2(x.y);
                Bpk2[bpk_idx(vk, vn + q + 2)] = split2(x.z);
                Bpk2[bpk_idx(vk, vn + q + 3)] = split2(x.w);
            }
        }
        __syncthreads();
        warp_chunk<2, 4>(Apk4, Bpk4, wrblk, wcblk, lane, acc);
    }

    const int r0 = (warp >> 1) * 32 + (lane >> 2);
    const int c0 = (warp & 1) * 32 + (lane & 3) * 2;
    float* ob = att + (size_t)(b * Tt + qt * 128) * HD + h * 64;
#pragma unroll
    for (int mi = 0; mi < 2; mi++)
#pragma unroll
        for (int nj = 0; nj < 4; nj++) {
            const int r = r0 + mi * 16, c = c0 + nj * 8;
            *(float2*)(ob + (size_t)r * HD + c)       = make_float2(acc[mi][nj][0], acc[mi][nj][1]);
            *(float2*)(ob + (size_t)(r + 8) * HD + c) = make_float2(acc[mi][nj][2], acc[mi][nj][3]);
        }
}

// ---------------------------------------------------------------------------
extern "C" void kernel_launch(void* const* d_in, const int* in_sizes, int n_in,
                              void* d_out, int out_size) {
    (void)in_sizes; (void)n_in; (void)out_size;

    const float* q  = (const float*)d_in[0];
    const float* k  = (const float*)d_in[1];
    const float* v  = (const float*)d_in[2];
    const float* Wq = (const float*)d_in[3];
    const float* Wk = (const float*)d_in[4];
    const float* Wv = (const float*)d_in[5];
    const float* Wo = (const float*)d_in[6];

    float* out = (float*)d_out;             // [B,T,D]
    float* wts = out + OUT_ELEMS;           // [B,H,T,T]

    void *pq, *pk, *pv, *pa;
    cudaGetSymbolAddress(&pq, g_qh);
    cudaGetSymbolAddress(&pk, g_kh);
    cudaGetSymbolAddress(&pv, g_vh);
    cudaGetSymbolAddress(&pa, g_att);
    float* qh  = (float*)pq;
    float* kh  = (float*)pk;
    float* vh  = (float*)pv;
    float* att = (float*)pa;

    // Raise dynamic smem limits (idempotent; not a stream op)
    cudaFuncSetAttribute(proj3_tc,   cudaFuncAttributeMaxDynamicSharedMemorySize, 65536);
    cudaFuncSetAttribute(outproj_tc, cudaFuncAttributeMaxDynamicSharedMemorySize, 65536);
    cudaFuncSetAttribute(rbf_tc,     cudaFuncAttributeMaxDynamicSharedMemorySize, 66560);
    cudaFuncSetAttribute(wv_tc,      cudaFuncAttributeMaxDynamicSharedMemorySize, 49152);

    dim3 blk(256);
    proj3_tc<<<dim3(HD / 128, BT / 128, 3), blk, 65536>>>(q, k, v, Wq, Wk, Wv, qh, kh, vh);
    rbf_tc<<<dim3(Tt / 128, Tt / 128, Bb * Hh), blk, 66560>>>(qh, kh, wts);
    wv_tc<<<dim3(Tt / 128, Bb * Hh), blk, 49152>>>(wts, vh, att);
    outproj_tc<<<dim3(Dd / 128, BT / 128), blk, 65536>>>(att, Wo, out);
}